// round 1
// baseline (speedup 1.0000x reference)
#include <cuda_runtime.h>

#define Nn 100000
#define Hh 128
#define Ee 1000000
#define DEe 16
#define EPSf 1e-5f

// ---------------- device scratch (allocation-free rule: device globals) ----------------
__device__ __align__(16) float g_B0[Nn*Hh];   // Ax / T1
__device__ __align__(16) float g_B1[Nn*Hh];   // h
__device__ __align__(16) float g_B2[Nn*Hh];   // z / h2
__device__ __align__(16) float g_B3[Nn*Hh];   // T2
__device__ __align__(16) float g_BX[Nn*DEe];  // Bx (edge_attr scatter)
__device__ __align__(16) float g_cnt[Nn];     // in-degree (col)
__device__ __align__(16) float g_dis[Nn];     // deg(row) -> rsqrt
__device__ __align__(16) float g_bn[512];     // sum[128], sumsq[128], scale[128], shift[128]

// ---------------- packed f32x2 fma (Blackwell) ----------------
__device__ __forceinline__ float2 ffma2(float2 a, float2 b, float2 c) {
    float2 d;
    asm("fma.rn.f32x2 %0, %1, %2, %3;"
        : "=l"(*reinterpret_cast<unsigned long long*>(&d))
        : "l"(*reinterpret_cast<unsigned long long*>(&a)),
          "l"(*reinterpret_cast<unsigned long long*>(&b)),
          "l"(*reinterpret_cast<unsigned long long*>(&c)));
    return d;
}

// ---------------- zero / init ----------------
__global__ void zero_all() {
    int i4 = blockIdx.x * blockDim.x + threadIdx.x;
    float4 z = make_float4(0.f, 0.f, 0.f, 0.f);
    if (i4 < Nn*32) reinterpret_cast<float4*>(g_B0)[i4] = z;
    if (i4 < Nn*4)  reinterpret_cast<float4*>(g_BX)[i4] = z;
    if (i4 < Nn/4) {
        reinterpret_cast<float4*>(g_cnt)[i4] = z;
        reinterpret_cast<float4*>(g_dis)[i4] = z;
    }
    if (i4 < 128)   reinterpret_cast<float4*>(g_bn)[i4] = z;
}

__global__ void zero_buf(float* __restrict__ p) {
    int i4 = blockIdx.x * blockDim.x + threadIdx.x;
    if (i4 < Nn*32) reinterpret_cast<float4*>(p)[i4] = make_float4(0.f,0.f,0.f,0.f);
}

// ---------------- edge scatter: Ax += x[row] @ col, Bx += ea @ col, counts ----------------
__global__ void edge_scatter0(const float* __restrict__ x, const int* __restrict__ ei,
                              const float* __restrict__ ea) {
    int e = blockIdx.x * 8 + (threadIdx.x >> 5);
    if (e >= Ee) return;
    int lane = threadIdx.x & 31;
    int r = __ldg(ei + e);
    int c = __ldg(ei + Ee + e);
    const float* xr = x + r * Hh;
    float* axc = g_B0 + c * Hh;
    #pragma unroll
    for (int j = 0; j < 4; j++) {
        atomicAdd(axc + lane + 32*j, __ldg(xr + lane + 32*j));
    }
    if (lane < DEe) atomicAdd(g_BX + c * DEe + lane, __ldg(ea + e * DEe + lane));
    if (lane == 0) {
        atomicAdd(g_cnt + c, 1.0f);
        atomicAdd(g_dis + r, 1.0f);   // out-degree accumulated here, converted later
    }
}

__global__ void deg2dis() {
    int n = blockIdx.x * blockDim.x + threadIdx.x;
    if (n < Nn) {
        float d = g_dis[n];
        g_dis[n] = (d > 0.f) ? rsqrtf(d) : 0.f;
    }
}

// ---------------- lhat scatter: dst[col] += coef * (-dis[row]*dis[col]) * z[row] ----------------
__global__ void lhat_scatter(const float* __restrict__ z, const int* __restrict__ ei,
                             float* __restrict__ dst, float coef) {
    int e = blockIdx.x * 8 + (threadIdx.x >> 5);
    if (e >= Ee) return;
    int lane = threadIdx.x & 31;
    int r = __ldg(ei + e);
    int c = __ldg(ei + Ee + e);
    float s = -coef * g_dis[r] * g_dis[c];
    if (s == 0.f) return;
    const float* zr = z + r * Hh;
    float* dc = dst + c * Hh;
    #pragma unroll
    for (int j = 0; j < 4; j++) {
        atomicAdd(dc + lane + 32*j, s * __ldg(zr + lane + 32*j));
    }
}

// ---------------- fused GEMM: out[N,128] = sum_p A_p[N,Kp] @ W_p[Kp,128] (+ epilogue) ----------
// mode 0: out = (acc + cnt*b) / max(cnt,1)           (interaction mean)
// mode 1: out = acc + b; accumulate BN sum/sumsq
// mode 2: out = relu(acc + b); optionally out2 = -out
__global__ __launch_bounds__(256, 2)
void gemm_fused(const float* __restrict__ A0, const float* __restrict__ W0, int K0,
                const float* __restrict__ A1, const float* __restrict__ W1, int K1,
                const float* __restrict__ A2, const float* __restrict__ W2, int K2,
                const float* __restrict__ bias, int mode,
                const float* __restrict__ cnt,
                float* __restrict__ out, float* __restrict__ out2,
                float* __restrict__ bnsum, float* __restrict__ bnsq) {
    __shared__ float As[32][132];   // transposed A tile: As[k][row]
    __shared__ float Ws[32][128];   // Ws[k][col]

    int t  = threadIdx.x;
    int tx = t & 15, ty = t >> 4;
    int r0 = blockIdx.x * 128;
    int c0 = tx * 8;

    float2 acc[8][4];
    #pragma unroll
    for (int i = 0; i < 8; i++)
        #pragma unroll
        for (int c = 0; c < 4; c++) acc[i][c] = make_float2(0.f, 0.f);

    const float* Ap[3] = {A0, A1, A2};
    const float* Wp[3] = {W0, W1, W2};
    int Kp[3] = {K0, K1, K2};

    int lrow = t >> 1;          // 0..127
    int lkh  = (t & 1) * 16;    // 0 or 16

    auto body = [&](int k) {
        float4 aA = *reinterpret_cast<const float4*>(&As[k][ty*8]);
        float4 aB = *reinterpret_cast<const float4*>(&As[k][ty*8 + 4]);
        float4 wA = *reinterpret_cast<const float4*>(&Ws[k][c0]);
        float4 wB = *reinterpret_cast<const float4*>(&Ws[k][c0 + 4]);
        float2 wv[4] = { make_float2(wA.x, wA.y), make_float2(wA.z, wA.w),
                         make_float2(wB.x, wB.y), make_float2(wB.z, wB.w) };
        float av[8] = {aA.x, aA.y, aA.z, aA.w, aB.x, aB.y, aB.z, aB.w};
        #pragma unroll
        for (int i = 0; i < 8; i++) {
            float2 pa = make_float2(av[i], av[i]);
            #pragma unroll
            for (int c = 0; c < 4; c++) acc[i][c] = ffma2(pa, wv[c], acc[i][c]);
        }
    };

    #pragma unroll
    for (int p = 0; p < 3; p++) {
        const float* A = Ap[p];
        const float* W = Wp[p];
        int KA = Kp[p];
        if (A == nullptr || KA <= 0) continue;
        for (int kt = 0; kt < KA; kt += 32) {
            int KC = min(32, KA - kt);
            // ---- load A tile (transposed into smem) ----
            {
                int grow = r0 + lrow;
                if (KC == 32) {
                    float4 t4[4];
                    if (grow < Nn) {
                        const float4* src = reinterpret_cast<const float4*>(A + grow*KA + kt + lkh);
                        t4[0] = src[0]; t4[1] = src[1]; t4[2] = src[2]; t4[3] = src[3];
                    } else {
                        float4 z = make_float4(0.f,0.f,0.f,0.f);
                        t4[0] = z; t4[1] = z; t4[2] = z; t4[3] = z;
                    }
                    const float* tf = reinterpret_cast<const float*>(t4);
                    #pragma unroll
                    for (int j = 0; j < 16; j++) As[lkh + j][lrow] = tf[j];
                } else {
                    #pragma unroll
                    for (int j = 0; j < 16; j++) {
                        int k = lkh + j;
                        if (k < KC) As[k][lrow] = (grow < Nn) ? A[grow*KA + kt + k] : 0.f;
                    }
                }
            }
            // ---- load W tile ----
            for (int q = t; q < KC * 32; q += 256) {   // float4 units: KC*128/4
                int k = q >> 5, c4 = q & 31;
                reinterpret_cast<float4*>(Ws[k])[c4] =
                    reinterpret_cast<const float4*>(W + (kt + k) * 128)[c4];
            }
            __syncthreads();
            if (KC == 32) {
                #pragma unroll 8
                for (int k = 0; k < 32; k++) body(k);
            } else {
                for (int k = 0; k < KC; k++) body(k);
            }
            __syncthreads();
        }
    }

    // ---- epilogue ----
    float4 b0 = *reinterpret_cast<const float4*>(bias + c0);
    float4 b1 = *reinterpret_cast<const float4*>(bias + c0 + 4);
    float bv[8] = {b0.x, b0.y, b0.z, b0.w, b1.x, b1.y, b1.z, b1.w};

    if (mode == 0) {
        #pragma unroll
        for (int i = 0; i < 8; i++) {
            int gr = r0 + ty*8 + i;
            if (gr < Nn) {
                float cv = cnt[gr];
                float rc = 1.0f / fmaxf(cv, 1.0f);
                float v[8];
                #pragma unroll
                for (int c = 0; c < 4; c++) {
                    v[2*c]   = (acc[i][c].x + cv * bv[2*c])   * rc;
                    v[2*c+1] = (acc[i][c].y + cv * bv[2*c+1]) * rc;
                }
                *reinterpret_cast<float4*>(out + gr*Hh + c0)     = make_float4(v[0],v[1],v[2],v[3]);
                *reinterpret_cast<float4*>(out + gr*Hh + c0 + 4) = make_float4(v[4],v[5],v[6],v[7]);
            }
        }
    } else if (mode == 1) {
        float cs[8], cq[8];
        #pragma unroll
        for (int j = 0; j < 8; j++) { cs[j] = 0.f; cq[j] = 0.f; }
        #pragma unroll
        for (int i = 0; i < 8; i++) {
            int gr = r0 + ty*8 + i;
            if (gr < Nn) {
                float v[8];
                #pragma unroll
                for (int c = 0; c < 4; c++) {
                    v[2*c]   = acc[i][c].x + bv[2*c];
                    v[2*c+1] = acc[i][c].y + bv[2*c+1];
                }
                *reinterpret_cast<float4*>(out + gr*Hh + c0)     = make_float4(v[0],v[1],v[2],v[3]);
                *reinterpret_cast<float4*>(out + gr*Hh + c0 + 4) = make_float4(v[4],v[5],v[6],v[7]);
                #pragma unroll
                for (int j = 0; j < 8; j++) { cs[j] += v[j]; cq[j] += v[j]*v[j]; }
            }
        }
        float (*red)[Hh] = reinterpret_cast<float(*)[Hh]>(Ws);
        #pragma unroll
        for (int j = 0; j < 8; j++) red[ty][c0 + j] = cs[j];
        __syncthreads();
        if (t < Hh) {
            float s = 0.f;
            #pragma unroll
            for (int y = 0; y < 16; y++) s += red[y][t];
            atomicAdd(bnsum + t, s);
        }
        __syncthreads();
        #pragma unroll
        for (int j = 0; j < 8; j++) red[ty][c0 + j] = cq[j];
        __syncthreads();
        if (t < Hh) {
            float s = 0.f;
            #pragma unroll
            for (int y = 0; y < 16; y++) s += red[y][t];
            atomicAdd(bnsq + t, s);
        }
    } else {
        #pragma unroll
        for (int i = 0; i < 8; i++) {
            int gr = r0 + ty*8 + i;
            if (gr < Nn) {
                float v[8];
                #pragma unroll
                for (int c = 0; c < 4; c++) {
                    v[2*c]   = fmaxf(acc[i][c].x + bv[2*c],   0.f);
                    v[2*c+1] = fmaxf(acc[i][c].y + bv[2*c+1], 0.f);
                }
                *reinterpret_cast<float4*>(out + gr*Hh + c0)     = make_float4(v[0],v[1],v[2],v[3]);
                *reinterpret_cast<float4*>(out + gr*Hh + c0 + 4) = make_float4(v[4],v[5],v[6],v[7]);
                if (out2 != nullptr) {
                    *reinterpret_cast<float4*>(out2 + gr*Hh + c0)     = make_float4(-v[0],-v[1],-v[2],-v[3]);
                    *reinterpret_cast<float4*>(out2 + gr*Hh + c0 + 4) = make_float4(-v[4],-v[5],-v[6],-v[7]);
                }
            }
        }
    }
}

// ---------------- BN finalize: scale/shift from accumulated stats ----------------
__global__ void bn_finalize(const float* __restrict__ g, const float* __restrict__ be) {
    int c = threadIdx.x;
    float m = g_bn[c] * (1.0f / (float)Nn);
    float q = g_bn[128 + c] * (1.0f / (float)Nn);
    float v = fmaxf(q - m*m, 0.f);
    float inv = rsqrtf(v + EPSf);
    float sc = g[c] * inv;
    g_bn[256 + c] = sc;
    g_bn[384 + c] = be[c] - m * sc;
    g_bn[c] = 0.f;          // rearm stats for the next BN
    g_bn[128 + c] = 0.f;
}

// ---------------- h = relu(scale*z + shift);  t2 = -h  ----------------
__global__ void bn_apply(const float* __restrict__ z, float* __restrict__ h, float* __restrict__ t2) {
    int i4 = blockIdx.x * blockDim.x + threadIdx.x;
    if (i4 >= Nn * 32) return;
    int c4 = i4 & 31;
    float4 zz = reinterpret_cast<const float4*>(z)[i4];
    float4 sc = reinterpret_cast<const float4*>(g_bn + 256)[c4];
    float4 sh = reinterpret_cast<const float4*>(g_bn + 384)[c4];
    float4 v;
    v.x = fmaxf(sc.x*zz.x + sh.x, 0.f);
    v.y = fmaxf(sc.y*zz.y + sh.y, 0.f);
    v.z = fmaxf(sc.z*zz.z + sh.z, 0.f);
    v.w = fmaxf(sc.w*zz.w + sh.w, 0.f);
    reinterpret_cast<float4*>(h)[i4] = v;
    reinterpret_cast<float4*>(t2)[i4] = make_float4(-v.x, -v.y, -v.z, -v.w);
}

// ---------------- head: out[n] = relu(bn(z)) . w_out + b_out ----------------
__global__ void final_out(const float* __restrict__ z, const float* __restrict__ wout,
                          const float* __restrict__ bout, float* __restrict__ out) {
    int w = blockIdx.x * 8 + (threadIdx.x >> 5);
    if (w >= Nn) return;
    int lane = threadIdx.x & 31;
    float s = 0.f;
    #pragma unroll
    for (int j = 0; j < 4; j++) {
        int c = lane + 32*j;
        float v = fmaxf(g_bn[256 + c] * z[w*Hh + c] + g_bn[384 + c], 0.f);
        s += v * wout[c];
    }
    #pragma unroll
    for (int o = 16; o > 0; o >>= 1) s += __shfl_xor_sync(0xffffffffu, s, o);
    if (lane == 0) out[w] = s + bout[0];
}

// ---------------- launch ----------------
extern "C" void kernel_launch(void* const* d_in, const int* in_sizes, int n_in,
                              void* d_out, int out_size) {
    const float* x      = (const float*)d_in[0];
    const int*   ei     = (const int*)  d_in[1];
    const float* ea     = (const float*)d_in[2];
    const float* w_int  = (const float*)d_in[3];
    const float* b_int  = (const float*)d_in[4];
    const float* w_pre  = (const float*)d_in[5];
    const float* b_pre  = (const float*)d_in[6];
    const float* gpre   = (const float*)d_in[7];
    const float* bepre  = (const float*)d_in[8];
    const float* c1w    = (const float*)d_in[9];
    const float* c1b    = (const float*)d_in[10];
    const float* c2w    = (const float*)d_in[11];
    const float* c2b    = (const float*)d_in[12];
    const float* w_post = (const float*)d_in[13];
    const float* b_post = (const float*)d_in[14];
    const float* gpost  = (const float*)d_in[15];
    const float* bepost = (const float*)d_in[16];
    const float* w_out  = (const float*)d_in[17];
    const float* b_out  = (const float*)d_in[18];
    float* out = (float*)d_out;

    float *B0, *B1, *B2, *B3, *BX, *cnt, *bn;
    cudaGetSymbolAddress((void**)&B0,  g_B0);
    cudaGetSymbolAddress((void**)&B1,  g_B1);
    cudaGetSymbolAddress((void**)&B2,  g_B2);
    cudaGetSymbolAddress((void**)&B3,  g_B3);
    cudaGetSymbolAddress((void**)&BX,  g_BX);
    cudaGetSymbolAddress((void**)&cnt, g_cnt);
    cudaGetSymbolAddress((void**)&bn,  g_bn);

    const int ZB = (Nn*32 + 255) / 256;   // 12500
    const int EB = (Ee + 7) / 8;          // 125000
    const int GB = (Nn + 127) / 128;      // 782

    zero_all<<<ZB, 256>>>();
    edge_scatter0<<<EB, 256>>>(x, ei, ea);
    deg2dis<<<(Nn + 255)/256, 256>>>();

    // interaction: h0 = (Ax@Wx + Bx@We + cnt*b) / max(cnt,1)   -> B1
    gemm_fused<<<GB, 256>>>(B0, w_int, 128, BX, w_int + 128*128, 16,
                            nullptr, nullptr, 0, b_int, 0, cnt,
                            B1, nullptr, nullptr, nullptr);
    // pre: z = h0 @ w_pre + b  (+BN stats) -> B2
    gemm_fused<<<GB, 256>>>(B1, w_pre, 128, nullptr, nullptr, 0,
                            nullptr, nullptr, 0, b_pre, 1, nullptr,
                            B2, nullptr, bn, bn + 128);
    bn_finalize<<<1, 128>>>(gpre, bepre);
    bn_apply<<<ZB, 256>>>(B2, B1, B3);        // B1 = h = relu(bn(z)); B3 = -h

    // cheb1
    zero_buf<<<ZB, 256>>>(B0);
    lhat_scatter<<<EB, 256>>>(B1, ei, B0, 1.0f);   // T1 = lhat(h)
    lhat_scatter<<<EB, 256>>>(B0, ei, B3, 2.0f);   // T2 = 2*lhat(T1) - h
    gemm_fused<<<GB, 256>>>(B1, c1w, 128, B0, c1w + 16384, 128,
                            B3, c1w + 32768, 128, c1b, 2, nullptr,
                            B2, B3, nullptr, nullptr); // B2 = h2 = relu(...); B3 = -h2

    // cheb2
    zero_buf<<<ZB, 256>>>(B0);
    lhat_scatter<<<EB, 256>>>(B2, ei, B0, 1.0f);
    lhat_scatter<<<EB, 256>>>(B0, ei, B3, 2.0f);
    gemm_fused<<<GB, 256>>>(B2, c2w, 128, B0, c2w + 16384, 128,
                            B3, c2w + 32768, 128, c2b, 2, nullptr,
                            B1, nullptr, nullptr, nullptr); // B1 = h3

    // post: z2 = h3 @ w_post + b (+BN stats) -> B2
    gemm_fused<<<GB, 256>>>(B1, w_post, 128, nullptr, nullptr, 0,
                            nullptr, nullptr, 0, b_post, 1, nullptr,
                            B2, nullptr, bn, bn + 128);
    bn_finalize<<<1, 128>>>(gpost, bepost);

    final_out<<<(Nn + 7)/8, 256>>>(B2, w_out, b_out, out);
}

// round 2
// speedup vs baseline: 1.4154x; 1.4154x over previous
#include <cuda_runtime.h>

#define Nn 100000
#define Hh 128
#define Ee 1000000
#define DEe 16
#define EPSf 1e-5f
#define NPART 98   // ceil(Nn/1024)

// ---------------- device scratch ----------------
__device__ __align__(16) float g_B0[Nn*Hh];   // Ax / T1
__device__ __align__(16) float g_B1[Nn*Hh];   // h
__device__ __align__(16) float g_B2[Nn*Hh];   // z / h2
__device__ __align__(16) float g_B3[Nn*Hh];   // T2
__device__ __align__(16) float g_BX[Nn*DEe];  // edge_attr aggregate
__device__ __align__(16) float g_cnt[Nn];     // in-degree (float)
__device__ __align__(16) float g_dis[Nn];     // rsqrt(out-degree)
__device__ __align__(16) float g_bn[512];     // sum, sumsq, scale, shift
__device__ __align__(16) int   g_cntin[Nn];   // in-degree hist (int)
__device__ __align__(16) int   g_degout[Nn];  // out-degree hist (int)
__device__ __align__(16) int   g_off[Nn];     // fill cursors
__device__ __align__(16) int   g_rowptr[Nn+1];
__device__ __align__(16) int   g_part[128];   // scan partials
__device__ __align__(16) int   g_srcidx[Ee];  // CSR: source node per sorted edge
__device__ __align__(16) int   g_eidx[Ee];    // CSR: original edge id

// ---------------- packed f32x2 fma ----------------
__device__ __forceinline__ float2 ffma2(float2 a, float2 b, float2 c) {
    float2 d;
    asm("fma.rn.f32x2 %0, %1, %2, %3;"
        : "=l"(*reinterpret_cast<unsigned long long*>(&d))
        : "l"(*reinterpret_cast<unsigned long long*>(&a)),
          "l"(*reinterpret_cast<unsigned long long*>(&b)),
          "l"(*reinterpret_cast<unsigned long long*>(&c)));
    return d;
}

// ---------------- init ----------------
__global__ void zero_init() {
    int i = blockIdx.x * blockDim.x + threadIdx.x;
    if (i < Nn) { g_cntin[i] = 0; g_degout[i] = 0; g_off[i] = 0; }
    if (i < 512) g_bn[i] = 0.f;
}

// ---------------- CSR build ----------------
__global__ void hist(const int* __restrict__ ei) {
    int e = blockIdx.x * blockDim.x + threadIdx.x;
    if (e < Ee) {
        atomicAdd(&g_cntin[__ldg(ei + Ee + e)], 1);
        atomicAdd(&g_degout[__ldg(ei + e)], 1);
    }
}

__global__ void scan1() {   // NPART blocks x 1024 threads
    __shared__ int wsum[32];
    int i = blockIdx.x * 1024 + threadIdx.x;
    int lane = threadIdx.x & 31, wid = threadIdx.x >> 5;
    int v = (i < Nn) ? g_cntin[i] : 0;
    int x = v;
    #pragma unroll
    for (int o = 1; o < 32; o <<= 1) {
        int y = __shfl_up_sync(0xffffffffu, x, o);
        if (lane >= o) x += y;
    }
    if (lane == 31) wsum[wid] = x;
    __syncthreads();
    if (wid == 0) {
        int s = wsum[lane];
        #pragma unroll
        for (int o = 1; o < 32; o <<= 1) {
            int y = __shfl_up_sync(0xffffffffu, s, o);
            if (lane >= o) s += y;
        }
        wsum[lane] = s;
    }
    __syncthreads();
    int base = (wid > 0) ? wsum[wid - 1] : 0;
    if (i < Nn) g_rowptr[i] = base + x - v;      // exclusive
    if (threadIdx.x == 0) g_part[blockIdx.x] = wsum[31];
}

__global__ void scan2() {   // 1 block, 128 threads
    __shared__ int sm[NPART];
    int t = threadIdx.x;
    if (t < NPART) sm[t] = g_part[t];
    __syncthreads();
    if (t == 0) {
        int s = 0;
        for (int i = 0; i < NPART; i++) { int v = sm[i]; sm[i] = s; s += v; }
    }
    __syncthreads();
    if (t < NPART) g_part[t] = sm[t];
}

__global__ void scan3() {
    int i = blockIdx.x * blockDim.x + threadIdx.x;
    if (i < Nn) g_rowptr[i] += g_part[i >> 10];
    if (i == 0) g_rowptr[Nn] = Ee;
}

__global__ void fill_csr(const int* __restrict__ ei) {
    int e = blockIdx.x * blockDim.x + threadIdx.x;
    if (e >= Ee) return;
    int c = __ldg(ei + Ee + e);
    int pos = g_rowptr[c] + atomicAdd(&g_off[c], 1);
    g_srcidx[pos] = __ldg(ei + e);
    g_eidx[pos] = e;
}

__global__ void deg2dis() {
    int n = blockIdx.x * blockDim.x + threadIdx.x;
    if (n < Nn) {
        int d = g_degout[n];
        g_dis[n] = (d > 0) ? rsqrtf((float)d) : 0.f;
    }
}

// ---------------- gather: interaction inputs ----------------
__global__ void gather_interact(const float* __restrict__ x, const float* __restrict__ ea) {
    int n = blockIdx.x * 8 + (threadIdx.x >> 5);
    if (n >= Nn) return;
    int lane = threadIdx.x & 31;
    int p0 = g_rowptr[n], p1 = g_rowptr[n + 1];
    float4 acc = make_float4(0.f, 0.f, 0.f, 0.f);
    float4 accE = make_float4(0.f, 0.f, 0.f, 0.f);
    const float4* x4 = reinterpret_cast<const float4*>(x);
    const float4* e4 = reinterpret_cast<const float4*>(ea);
    int p = p0;
    for (; p + 1 < p1; p += 2) {
        int s0 = __ldg(g_srcidx + p),     e0 = __ldg(g_eidx + p);
        int s1 = __ldg(g_srcidx + p + 1), e1 = __ldg(g_eidx + p + 1);
        float4 v0 = __ldg(x4 + s0 * 32 + lane);
        float4 v1 = __ldg(x4 + s1 * 32 + lane);
        acc.x += v0.x + v1.x; acc.y += v0.y + v1.y;
        acc.z += v0.z + v1.z; acc.w += v0.w + v1.w;
        if (lane < 4) {
            float4 a0 = __ldg(e4 + e0 * 4 + lane);
            float4 a1 = __ldg(e4 + e1 * 4 + lane);
            accE.x += a0.x + a1.x; accE.y += a0.y + a1.y;
            accE.z += a0.z + a1.z; accE.w += a0.w + a1.w;
        }
    }
    if (p < p1) {
        int s0 = __ldg(g_srcidx + p), e0 = __ldg(g_eidx + p);
        float4 v0 = __ldg(x4 + s0 * 32 + lane);
        acc.x += v0.x; acc.y += v0.y; acc.z += v0.z; acc.w += v0.w;
        if (lane < 4) {
            float4 a0 = __ldg(e4 + e0 * 4 + lane);
            accE.x += a0.x; accE.y += a0.y; accE.z += a0.z; accE.w += a0.w;
        }
    }
    reinterpret_cast<float4*>(g_B0)[n * 32 + lane] = acc;
    if (lane < 4) reinterpret_cast<float4*>(g_BX)[n * 4 + lane] = accE;
    if (lane == 0) g_cnt[n] = (float)(p1 - p0);
}

// ---------------- gather: scaled-Laplacian propagation ----------------
// dst[n] = coef * sum_e(-dis[n]*dis[src]) * src_feat[src]   (- sub[n] if sub)
__global__ void gather_lhat(const float* __restrict__ src, float* __restrict__ dst,
                            const float* __restrict__ sub, float coef) {
    int n = blockIdx.x * 8 + (threadIdx.x >> 5);
    if (n >= Nn) return;
    int lane = threadIdx.x & 31;
    int p0 = g_rowptr[n], p1 = g_rowptr[n + 1];
    float dd = -coef * g_dis[n];
    float4 acc = make_float4(0.f, 0.f, 0.f, 0.f);
    const float4* s4 = reinterpret_cast<const float4*>(src);
    int p = p0;
    for (; p + 1 < p1; p += 2) {
        int s0 = __ldg(g_srcidx + p);
        int s1 = __ldg(g_srcidx + p + 1);
        float c0 = dd * __ldg(g_dis + s0);
        float c1 = dd * __ldg(g_dis + s1);
        float4 v0 = __ldg(s4 + s0 * 32 + lane);
        float4 v1 = __ldg(s4 + s1 * 32 + lane);
        acc.x += c0 * v0.x + c1 * v1.x;
        acc.y += c0 * v0.y + c1 * v1.y;
        acc.z += c0 * v0.z + c1 * v1.z;
        acc.w += c0 * v0.w + c1 * v1.w;
    }
    if (p < p1) {
        int s0 = __ldg(g_srcidx + p);
        float c0 = dd * __ldg(g_dis + s0);
        float4 v0 = __ldg(s4 + s0 * 32 + lane);
        acc.x += c0 * v0.x; acc.y += c0 * v0.y;
        acc.z += c0 * v0.z; acc.w += c0 * v0.w;
    }
    if (sub != nullptr) {
        float4 h = reinterpret_cast<const float4*>(sub)[n * 32 + lane];
        acc.x -= h.x; acc.y -= h.y; acc.z -= h.z; acc.w -= h.w;
    }
    reinterpret_cast<float4*>(dst)[n * 32 + lane] = acc;
}

// ---------------- fused GEMM (unchanged core) ----------------
__global__ __launch_bounds__(256, 2)
void gemm_fused(const float* __restrict__ A0, const float* __restrict__ W0, int K0,
                const float* __restrict__ A1, const float* __restrict__ W1, int K1,
                const float* __restrict__ A2, const float* __restrict__ W2, int K2,
                const float* __restrict__ bias, int mode,
                const float* __restrict__ cnt,
                float* __restrict__ out,
                float* __restrict__ bnsum, float* __restrict__ bnsq) {
    __shared__ float As[32][132];
    __shared__ float Ws[32][128];

    int t  = threadIdx.x;
    int tx = t & 15, ty = t >> 4;
    int r0 = blockIdx.x * 128;
    int c0 = tx * 8;

    float2 acc[8][4];
    #pragma unroll
    for (int i = 0; i < 8; i++)
        #pragma unroll
        for (int c = 0; c < 4; c++) acc[i][c] = make_float2(0.f, 0.f);

    const float* Ap[3] = {A0, A1, A2};
    const float* Wp[3] = {W0, W1, W2};
    int Kp[3] = {K0, K1, K2};

    int lrow = t >> 1;
    int lkh  = (t & 1) * 16;

    auto body = [&](int k) {
        float4 aA = *reinterpret_cast<const float4*>(&As[k][ty*8]);
        float4 aB = *reinterpret_cast<const float4*>(&As[k][ty*8 + 4]);
        float4 wA = *reinterpret_cast<const float4*>(&Ws[k][c0]);
        float4 wB = *reinterpret_cast<const float4*>(&Ws[k][c0 + 4]);
        float2 wv[4] = { make_float2(wA.x, wA.y), make_float2(wA.z, wA.w),
                         make_float2(wB.x, wB.y), make_float2(wB.z, wB.w) };
        float av[8] = {aA.x, aA.y, aA.z, aA.w, aB.x, aB.y, aB.z, aB.w};
        #pragma unroll
        for (int i = 0; i < 8; i++) {
            float2 pa = make_float2(av[i], av[i]);
            #pragma unroll
            for (int c = 0; c < 4; c++) acc[i][c] = ffma2(pa, wv[c], acc[i][c]);
        }
    };

    #pragma unroll
    for (int p = 0; p < 3; p++) {
        const float* A = Ap[p];
        const float* W = Wp[p];
        int KA = Kp[p];
        if (A == nullptr || KA <= 0) continue;
        for (int kt = 0; kt < KA; kt += 32) {
            int KC = min(32, KA - kt);
            {
                int grow = r0 + lrow;
                if (KC == 32) {
                    float4 t4[4];
                    if (grow < Nn) {
                        const float4* src = reinterpret_cast<const float4*>(A + grow*KA + kt + lkh);
                        t4[0] = src[0]; t4[1] = src[1]; t4[2] = src[2]; t4[3] = src[3];
                    } else {
                        float4 z = make_float4(0.f,0.f,0.f,0.f);
                        t4[0] = z; t4[1] = z; t4[2] = z; t4[3] = z;
                    }
                    const float* tf = reinterpret_cast<const float*>(t4);
                    #pragma unroll
                    for (int j = 0; j < 16; j++) As[lkh + j][lrow] = tf[j];
                } else {
                    #pragma unroll
                    for (int j = 0; j < 16; j++) {
                        int k = lkh + j;
                        if (k < KC) As[k][lrow] = (grow < Nn) ? A[grow*KA + kt + k] : 0.f;
                    }
                }
            }
            for (int q = t; q < KC * 32; q += 256) {
                int k = q >> 5, c4 = q & 31;
                reinterpret_cast<float4*>(Ws[k])[c4] =
                    reinterpret_cast<const float4*>(W + (kt + k) * 128)[c4];
            }
            __syncthreads();
            if (KC == 32) {
                #pragma unroll 8
                for (int k = 0; k < 32; k++) body(k);
            } else {
                for (int k = 0; k < KC; k++) body(k);
            }
            __syncthreads();
        }
    }

    float4 b0 = *reinterpret_cast<const float4*>(bias + c0);
    float4 b1 = *reinterpret_cast<const float4*>(bias + c0 + 4);
    float bv[8] = {b0.x, b0.y, b0.z, b0.w, b1.x, b1.y, b1.z, b1.w};

    if (mode == 0) {
        #pragma unroll
        for (int i = 0; i < 8; i++) {
            int gr = r0 + ty*8 + i;
            if (gr < Nn) {
                float cv = cnt[gr];
                float rc = 1.0f / fmaxf(cv, 1.0f);
                float v[8];
                #pragma unroll
                for (int c = 0; c < 4; c++) {
                    v[2*c]   = (acc[i][c].x + cv * bv[2*c])   * rc;
                    v[2*c+1] = (acc[i][c].y + cv * bv[2*c+1]) * rc;
                }
                *reinterpret_cast<float4*>(out + gr*Hh + c0)     = make_float4(v[0],v[1],v[2],v[3]);
                *reinterpret_cast<float4*>(out + gr*Hh + c0 + 4) = make_float4(v[4],v[5],v[6],v[7]);
            }
        }
    } else if (mode == 1) {
        float cs[8], cq[8];
        #pragma unroll
        for (int j = 0; j < 8; j++) { cs[j] = 0.f; cq[j] = 0.f; }
        #pragma unroll
        for (int i = 0; i < 8; i++) {
            int gr = r0 + ty*8 + i;
            if (gr < Nn) {
                float v[8];
                #pragma unroll
                for (int c = 0; c < 4; c++) {
                    v[2*c]   = acc[i][c].x + bv[2*c];
                    v[2*c+1] = acc[i][c].y + bv[2*c+1];
                }
                *reinterpret_cast<float4*>(out + gr*Hh + c0)     = make_float4(v[0],v[1],v[2],v[3]);
                *reinterpret_cast<float4*>(out + gr*Hh + c0 + 4) = make_float4(v[4],v[5],v[6],v[7]);
                #pragma unroll
                for (int j = 0; j < 8; j++) { cs[j] += v[j]; cq[j] += v[j]*v[j]; }
            }
        }
        float (*red)[Hh] = reinterpret_cast<float(*)[Hh]>(Ws);
        #pragma unroll
        for (int j = 0; j < 8; j++) red[ty][c0 + j] = cs[j];
        __syncthreads();
        if (t < Hh) {
            float s = 0.f;
            #pragma unroll
            for (int y = 0; y < 16; y++) s += red[y][t];
            atomicAdd(bnsum + t, s);
        }
        __syncthreads();
        #pragma unroll
        for (int j = 0; j < 8; j++) red[ty][c0 + j] = cq[j];
        __syncthreads();
        if (t < Hh) {
            float s = 0.f;
            #pragma unroll
            for (int y = 0; y < 16; y++) s += red[y][t];
            atomicAdd(bnsq + t, s);
        }
    } else {
        #pragma unroll
        for (int i = 0; i < 8; i++) {
            int gr = r0 + ty*8 + i;
            if (gr < Nn) {
                float v[8];
                #pragma unroll
                for (int c = 0; c < 4; c++) {
                    v[2*c]   = fmaxf(acc[i][c].x + bv[2*c],   0.f);
                    v[2*c+1] = fmaxf(acc[i][c].y + bv[2*c+1], 0.f);
                }
                *reinterpret_cast<float4*>(out + gr*Hh + c0)     = make_float4(v[0],v[1],v[2],v[3]);
                *reinterpret_cast<float4*>(out + gr*Hh + c0 + 4) = make_float4(v[4],v[5],v[6],v[7]);
            }
        }
    }
}

// ---------------- BN finalize ----------------
__global__ void bn_finalize(const float* __restrict__ g, const float* __restrict__ be) {
    int c = threadIdx.x;
    float m = g_bn[c] * (1.0f / (float)Nn);
    float q = g_bn[128 + c] * (1.0f / (float)Nn);
    float v = fmaxf(q - m*m, 0.f);
    float inv = rsqrtf(v + EPSf);
    float sc = g[c] * inv;
    g_bn[256 + c] = sc;
    g_bn[384 + c] = be[c] - m * sc;
    g_bn[c] = 0.f;
    g_bn[128 + c] = 0.f;
}

// ---------------- h = relu(scale*z + shift) ----------------
__global__ void bn_apply(const float* __restrict__ z, float* __restrict__ h) {
    int i4 = blockIdx.x * blockDim.x + threadIdx.x;
    if (i4 >= Nn * 32) return;
    int c4 = i4 & 31;
    float4 zz = reinterpret_cast<const float4*>(z)[i4];
    float4 sc = reinterpret_cast<const float4*>(g_bn + 256)[c4];
    float4 sh = reinterpret_cast<const float4*>(g_bn + 384)[c4];
    float4 v;
    v.x = fmaxf(sc.x*zz.x + sh.x, 0.f);
    v.y = fmaxf(sc.y*zz.y + sh.y, 0.f);
    v.z = fmaxf(sc.z*zz.z + sh.z, 0.f);
    v.w = fmaxf(sc.w*zz.w + sh.w, 0.f);
    reinterpret_cast<float4*>(h)[i4] = v;
}

// ---------------- head ----------------
__global__ void final_out(const float* __restrict__ z, const float* __restrict__ wout,
                          const float* __restrict__ bout, float* __restrict__ out) {
    int w = blockIdx.x * 8 + (threadIdx.x >> 5);
    if (w >= Nn) return;
    int lane = threadIdx.x & 31;
    float s = 0.f;
    #pragma unroll
    for (int j = 0; j < 4; j++) {
        int c = lane + 32*j;
        float v = fmaxf(g_bn[256 + c] * z[w*Hh + c] + g_bn[384 + c], 0.f);
        s += v * wout[c];
    }
    #pragma unroll
    for (int o = 16; o > 0; o >>= 1) s += __shfl_xor_sync(0xffffffffu, s, o);
    if (lane == 0) out[w] = s + bout[0];
}

// ---------------- launch ----------------
extern "C" void kernel_launch(void* const* d_in, const int* in_sizes, int n_in,
                              void* d_out, int out_size) {
    const float* x      = (const float*)d_in[0];
    const int*   ei     = (const int*)  d_in[1];
    const float* ea     = (const float*)d_in[2];
    const float* w_int  = (const float*)d_in[3];
    const float* b_int  = (const float*)d_in[4];
    const float* w_pre  = (const float*)d_in[5];
    const float* b_pre  = (const float*)d_in[6];
    const float* gpre   = (const float*)d_in[7];
    const float* bepre  = (const float*)d_in[8];
    const float* c1w    = (const float*)d_in[9];
    const float* c1b    = (const float*)d_in[10];
    const float* c2w    = (const float*)d_in[11];
    const float* c2b    = (const float*)d_in[12];
    const float* w_post = (const float*)d_in[13];
    const float* b_post = (const float*)d_in[14];
    const float* gpost  = (const float*)d_in[15];
    const float* bepost = (const float*)d_in[16];
    const float* w_out  = (const float*)d_in[17];
    const float* b_out  = (const float*)d_in[18];
    float* out = (float*)d_out;

    float *B0, *B1, *B2, *B3, *BX, *cnt, *bn;
    cudaGetSymbolAddress((void**)&B0,  g_B0);
    cudaGetSymbolAddress((void**)&B1,  g_B1);
    cudaGetSymbolAddress((void**)&B2,  g_B2);
    cudaGetSymbolAddress((void**)&B3,  g_B3);
    cudaGetSymbolAddress((void**)&BX,  g_BX);
    cudaGetSymbolAddress((void**)&cnt, g_cnt);
    cudaGetSymbolAddress((void**)&bn,  g_bn);

    const int EB = (Ee + 255) / 256;      // 3907
    const int GB = (Nn + 127) / 128;      // 782
    const int WB = (Nn + 7) / 8;          // 12500 (warp-per-node)
    const int NB = (Nn + 255) / 256;      // 391

    // CSR build
    zero_init<<<NB, 256>>>();
    hist<<<EB, 256>>>(ei);
    scan1<<<NPART, 1024>>>();
    scan2<<<1, 128>>>();
    scan3<<<NB, 256>>>();
    fill_csr<<<EB, 256>>>(ei);
    deg2dis<<<NB, 256>>>();

    // interaction gather + GEMM -> B1
    gather_interact<<<WB, 256>>>(x, ea);
    gemm_fused<<<GB, 256>>>(B0, w_int, 128, BX, w_int + 128*128, 16,
                            nullptr, nullptr, 0, b_int, 0, cnt,
                            B1, nullptr, nullptr);
    // pre
    gemm_fused<<<GB, 256>>>(B1, w_pre, 128, nullptr, nullptr, 0,
                            nullptr, nullptr, 0, b_pre, 1, nullptr,
                            B2, bn, bn + 128);
    bn_finalize<<<1, 128>>>(gpre, bepre);
    bn_apply<<<(Nn*32 + 255)/256, 256>>>(B2, B1);   // B1 = h

    // cheb1
    gather_lhat<<<WB, 256>>>(B1, B0, nullptr, 1.0f);   // T1
    gather_lhat<<<WB, 256>>>(B0, B3, B1, 2.0f);        // T2 = 2*lhat(T1) - h
    gemm_fused<<<GB, 256>>>(B1, c1w, 128, B0, c1w + 16384, 128,
                            B3, c1w + 32768, 128, c1b, 2, nullptr,
                            B2, nullptr, nullptr);     // B2 = h2

    // cheb2
    gather_lhat<<<WB, 256>>>(B2, B0, nullptr, 1.0f);
    gather_lhat<<<WB, 256>>>(B0, B3, B2, 2.0f);
    gemm_fused<<<GB, 256>>>(B2, c2w, 128, B0, c2w + 16384, 128,
                            B3, c2w + 32768, 128, c2b, 2, nullptr,
                            B1, nullptr, nullptr);     // B1 = h3

    // post + head
    gemm_fused<<<GB, 256>>>(B1, w_post, 128, nullptr, nullptr, 0,
                            nullptr, nullptr, 0, b_post, 1, nullptr,
                            B2, bn, bn + 128);
    bn_finalize<<<1, 128>>>(gpost, bepost);
    final_out<<<WB, 256>>>(B2, w_out, b_out, out);
}

// round 4
// speedup vs baseline: 1.4683x; 1.0374x over previous
#include <cuda_runtime.h>
#include <cstdint>

#define Nn 100000
#define Hh 128
#define Ee 1000000
#define DEe 16
#define EPSf 1e-5f
#define NPART 98   // ceil(Nn/1024)

// ---------------- device scratch ----------------
__device__ __align__(16) float g_B0[Nn*Hh];
__device__ __align__(16) float g_B1[Nn*Hh];
__device__ __align__(16) float g_B2[Nn*Hh];
__device__ __align__(16) float g_B3[Nn*Hh];
__device__ __align__(16) float g_BX[Nn*DEe];
__device__ __align__(16) float g_cnt[Nn];
__device__ __align__(16) float g_dis[Nn];
__device__ __align__(16) float g_bn[512];
__device__ __align__(16) int   g_cntin[Nn];    // in-degree hist; reused as fill cursor
__device__ __align__(16) int   g_degout[Nn];
__device__ __align__(16) int   g_rowptr[Nn+1];
__device__ __align__(16) int   g_part[128];
__device__ __align__(16) int4  g_pair[Ee];     // (src, eid, dis_bits, 0) per sorted edge

// ---------------- packed f32x2 fma ----------------
__device__ __forceinline__ float2 ffma2(float2 a, float2 b, float2 c) {
    float2 d;
    asm("fma.rn.f32x2 %0, %1, %2, %3;"
        : "=l"(*reinterpret_cast<unsigned long long*>(&d))
        : "l"(*reinterpret_cast<unsigned long long*>(&a)),
          "l"(*reinterpret_cast<unsigned long long*>(&b)),
          "l"(*reinterpret_cast<unsigned long long*>(&c)));
    return d;
}

__device__ __forceinline__ uint32_t smem_u32(const void* p) {
    uint32_t a;
    asm("{ .reg .u64 t; cvta.to.shared.u64 t, %1; cvt.u32.u64 %0, t; }" : "=r"(a) : "l"(p));
    return a;
}
__device__ __forceinline__ void cpasync16(uint32_t dst, const void* src, int bytes) {
    asm volatile("cp.async.cg.shared.global [%0], [%1], 16, %2;" :: "r"(dst), "l"(src), "r"(bytes));
}

// ---------------- init ----------------
__global__ void zero_init() {
    int i = blockIdx.x * blockDim.x + threadIdx.x;
    if (i < Nn) { g_cntin[i] = 0; g_degout[i] = 0; }
    if (i < 512) g_bn[i] = 0.f;
}

// ---------------- CSR build ----------------
__global__ void hist(const int* __restrict__ ei) {
    int e = blockIdx.x * blockDim.x + threadIdx.x;
    if (e < Ee) {
        atomicAdd(&g_cntin[__ldg(ei + Ee + e)], 1);
        atomicAdd(&g_degout[__ldg(ei + e)], 1);
    }
}

__global__ void scan1() {
    __shared__ int wsum[32];
    int i = blockIdx.x * 1024 + threadIdx.x;
    int lane = threadIdx.x & 31, wid = threadIdx.x >> 5;
    int v = (i < Nn) ? g_cntin[i] : 0;
    int x = v;
    #pragma unroll
    for (int o = 1; o < 32; o <<= 1) {
        int y = __shfl_up_sync(0xffffffffu, x, o);
        if (lane >= o) x += y;
    }
    if (lane == 31) wsum[wid] = x;
    __syncthreads();
    if (wid == 0) {
        int s = wsum[lane];
        #pragma unroll
        for (int o = 1; o < 32; o <<= 1) {
            int y = __shfl_up_sync(0xffffffffu, s, o);
            if (lane >= o) s += y;
        }
        wsum[lane] = s;
    }
    __syncthreads();
    int base = (wid > 0) ? wsum[wid - 1] : 0;
    if (i < Nn) g_rowptr[i] = base + x - v;
    if (threadIdx.x == 0) g_part[blockIdx.x] = wsum[31];
}

__global__ void scan2() {
    __shared__ int sm[NPART];
    int t = threadIdx.x;
    if (t < NPART) sm[t] = g_part[t];
    __syncthreads();
    if (t == 0) {
        int s = 0;
        for (int i = 0; i < NPART; i++) { int v = sm[i]; sm[i] = s; s += v; }
    }
    __syncthreads();
    if (t < NPART) g_part[t] = sm[t];
}

__global__ void scan3_dis() {
    int i = blockIdx.x * blockDim.x + threadIdx.x;
    if (i < Nn) {
        g_rowptr[i] += g_part[i >> 10];
        int d = g_degout[i];
        g_dis[i] = (d > 0) ? rsqrtf((float)d) : 0.f;
    }
    if (i == 0) g_rowptr[Nn] = Ee;
}

__global__ void fill_csr(const int* __restrict__ ei) {
    int e = blockIdx.x * blockDim.x + threadIdx.x;
    if (e >= Ee) return;
    int r = __ldg(ei + e);
    int c = __ldg(ei + Ee + e);
    int pos = g_rowptr[c] + atomicAdd(&g_cntin[c], -1) - 1;
    int4 pk;
    pk.x = r;
    pk.y = e;
    pk.z = __float_as_int(g_dis[r]);
    pk.w = 0;
    g_pair[pos] = pk;
}

// ---------------- gather: interaction inputs ----------------
__global__ void gather_interact(const float* __restrict__ x, const float* __restrict__ ea) {
    int n = blockIdx.x * 8 + (threadIdx.x >> 5);
    if (n >= Nn) return;
    int lane = threadIdx.x & 31;
    int p0 = __ldg(g_rowptr + n), p1 = __ldg(g_rowptr + n + 1);
    float4 acc = make_float4(0.f, 0.f, 0.f, 0.f);
    float4 accE = make_float4(0.f, 0.f, 0.f, 0.f);
    const float4* x4 = reinterpret_cast<const float4*>(x);
    const float4* e4 = reinterpret_cast<const float4*>(ea);
    const int4* pr = g_pair;
    int p = p0;
    for (; p + 4 <= p1; p += 4) {
        int4 q0 = __ldg(pr + p), q1 = __ldg(pr + p + 1);
        int4 q2 = __ldg(pr + p + 2), q3 = __ldg(pr + p + 3);
        float4 v0 = __ldg(x4 + q0.x * 32 + lane);
        float4 v1 = __ldg(x4 + q1.x * 32 + lane);
        float4 v2 = __ldg(x4 + q2.x * 32 + lane);
        float4 v3 = __ldg(x4 + q3.x * 32 + lane);
        acc.x += (v0.x + v1.x) + (v2.x + v3.x);
        acc.y += (v0.y + v1.y) + (v2.y + v3.y);
        acc.z += (v0.z + v1.z) + (v2.z + v3.z);
        acc.w += (v0.w + v1.w) + (v2.w + v3.w);
        if (lane < 4) {
            float4 a0 = __ldg(e4 + q0.y * 4 + lane);
            float4 a1 = __ldg(e4 + q1.y * 4 + lane);
            float4 a2 = __ldg(e4 + q2.y * 4 + lane);
            float4 a3 = __ldg(e4 + q3.y * 4 + lane);
            accE.x += (a0.x + a1.x) + (a2.x + a3.x);
            accE.y += (a0.y + a1.y) + (a2.y + a3.y);
            accE.z += (a0.z + a1.z) + (a2.z + a3.z);
            accE.w += (a0.w + a1.w) + (a2.w + a3.w);
        }
    }
    for (; p < p1; p++) {
        int4 q0 = __ldg(pr + p);
        float4 v0 = __ldg(x4 + q0.x * 32 + lane);
        acc.x += v0.x; acc.y += v0.y; acc.z += v0.z; acc.w += v0.w;
        if (lane < 4) {
            float4 a0 = __ldg(e4 + q0.y * 4 + lane);
            accE.x += a0.x; accE.y += a0.y; accE.z += a0.z; accE.w += a0.w;
        }
    }
    reinterpret_cast<float4*>(g_B0)[n * 32 + lane] = acc;
    if (lane < 4) reinterpret_cast<float4*>(g_BX)[n * 4 + lane] = accE;
    if (lane == 0) g_cnt[n] = (float)(p1 - p0);
}

// ---------------- gather: scaled-Laplacian propagation ----------------
__global__ void gather_lhat(const float* __restrict__ src, float* __restrict__ dst,
                            const float* __restrict__ sub, float coef) {
    int n = blockIdx.x * 8 + (threadIdx.x >> 5);
    if (n >= Nn) return;
    int lane = threadIdx.x & 31;
    int p0 = __ldg(g_rowptr + n), p1 = __ldg(g_rowptr + n + 1);
    float dd = -coef * g_dis[n];
    float4 acc = make_float4(0.f, 0.f, 0.f, 0.f);
    const float4* s4 = reinterpret_cast<const float4*>(src);
    const int4* pr = g_pair;
    int p = p0;
    for (; p + 4 <= p1; p += 4) {
        int4 q0 = __ldg(pr + p), q1 = __ldg(pr + p + 1);
        int4 q2 = __ldg(pr + p + 2), q3 = __ldg(pr + p + 3);
        float4 v0 = __ldg(s4 + q0.x * 32 + lane);
        float4 v1 = __ldg(s4 + q1.x * 32 + lane);
        float4 v2 = __ldg(s4 + q2.x * 32 + lane);
        float4 v3 = __ldg(s4 + q3.x * 32 + lane);
        float c0 = dd * __int_as_float(q0.z);
        float c1 = dd * __int_as_float(q1.z);
        float c2 = dd * __int_as_float(q2.z);
        float c3 = dd * __int_as_float(q3.z);
        acc.x += c0*v0.x + c1*v1.x + c2*v2.x + c3*v3.x;
        acc.y += c0*v0.y + c1*v1.y + c2*v2.y + c3*v3.y;
        acc.z += c0*v0.z + c1*v1.z + c2*v2.z + c3*v3.z;
        acc.w += c0*v0.w + c1*v1.w + c2*v2.w + c3*v3.w;
    }
    for (; p < p1; p++) {
        int4 q0 = __ldg(pr + p);
        float c0 = dd * __int_as_float(q0.z);
        float4 v0 = __ldg(s4 + q0.x * 32 + lane);
        acc.x += c0 * v0.x; acc.y += c0 * v0.y;
        acc.z += c0 * v0.z; acc.w += c0 * v0.w;
    }
    if (sub != nullptr) {
        float4 h = reinterpret_cast<const float4*>(sub)[n * 32 + lane];
        acc.x -= h.x; acc.y -= h.y; acc.z -= h.z; acc.w -= h.w;
    }
    reinterpret_cast<float4*>(dst)[n * 32 + lane] = acc;
}

// ---------------- double-buffered GEMM via cp.async ----------------
// smem layout (dynamic, 64KB): As[2][128*32] then Ws[2][32*128]
__global__ __launch_bounds__(256, 2)
void gemm2(const float* __restrict__ A0, const float* __restrict__ W0, int K0,
           const float* __restrict__ A1, const float* __restrict__ W1, int K1,
           const float* __restrict__ A2, const float* __restrict__ W2, int K2,
           const float* __restrict__ bias, int mode,
           const float* __restrict__ cnt,
           float* __restrict__ out,
           float* __restrict__ bnsum, float* __restrict__ bnsq) {
    extern __shared__ float sm[];
    float* AsBase = sm;           // 8192 floats
    float* WsBase = sm + 8192;    // 8192 floats

    int t  = threadIdx.x;
    int tx = t & 15, ty = t >> 4;
    int r0 = blockIdx.x * 128;
    int c0 = tx * 8;
    int ry = ty * 8;

    // tile descriptors (max 12)
    const float* tA[12]; const float* tW[12]; int tKA[12]; int tkt[12];
    int nt = 0;
    {
        const float* Ap[3] = {A0, A1, A2};
        const float* Wp[3] = {W0, W1, W2};
        int Kp[3] = {K0, K1, K2};
        for (int p = 0; p < 3; p++) {
            if (Ap[p] == nullptr || Kp[p] <= 0) continue;
            for (int kt = 0; kt < Kp[p]; kt += 32) {
                tA[nt] = Ap[p]; tW[nt] = Wp[p]; tKA[nt] = Kp[p]; tkt[nt] = kt; nt++;
            }
        }
    }

    uint32_t asAddr = smem_u32(AsBase);
    uint32_t wsAddr = smem_u32(WsBase);

    // stage tile i into buffer b
    auto stage = [&](int b, int i) {
        const float* A = tA[i]; const float* W = tW[i];
        int KA = tKA[i], kt = tkt[i];
        int KC = KA - kt; if (KC > 32) KC = 32;
        uint32_t ad = asAddr + (uint32_t)b * 16384;
        uint32_t wd = wsAddr + (uint32_t)b * 16384;
        #pragma unroll
        for (int j = 0; j < 4; j++) {
            int q = t + j * 256;            // 0..1023
            int row = q >> 3, seg = q & 7;  // A: row in tile, 16B segment
            int grow = r0 + row;
            int ok = (grow < Nn && seg * 4 < KC) ? 16 : 0;
            cpasync16(ad + (uint32_t)(row * 128 + seg * 16),
                      A + (size_t)grow * KA + kt + seg * 4, ok);
            int k = q >> 5, c4 = q & 31;    // W: k row, 16B segment
            int okw = (k < KC) ? 16 : 0;
            cpasync16(wd + (uint32_t)(k * 512 + c4 * 16),
                      W + (size_t)(kt + k) * 128 + c4 * 4, okw);
        }
        asm volatile("cp.async.commit_group;");
    };

    float2 acc[8][4];
    #pragma unroll
    for (int i = 0; i < 8; i++)
        #pragma unroll
        for (int c = 0; c < 4; c++) acc[i][c] = make_float2(0.f, 0.f);

    int buf = 0;
    stage(0, 0);
    for (int i = 0; i < nt; i++) {
        if (i + 1 < nt) {
            stage(buf ^ 1, i + 1);
            asm volatile("cp.async.wait_group 1;");
        } else {
            asm volatile("cp.async.wait_group 0;");
        }
        __syncthreads();
        const float* Ab = AsBase + buf * 4096;
        const float* Wb = WsBase + buf * 4096;
        #pragma unroll
        for (int k4 = 0; k4 < 8; k4++) {
            float4 ar[8];
            #pragma unroll
            for (int r = 0; r < 8; r++)
                ar[r] = *reinterpret_cast<const float4*>(Ab + (ry + r) * 32 + k4 * 4);
            #pragma unroll
            for (int kk = 0; kk < 4; kk++) {
                int k = k4 * 4 + kk;
                float4 wA = *reinterpret_cast<const float4*>(Wb + k * 128 + c0);
                float4 wB = *reinterpret_cast<const float4*>(Wb + k * 128 + c0 + 4);
                float2 wv[4] = { make_float2(wA.x, wA.y), make_float2(wA.z, wA.w),
                                 make_float2(wB.x, wB.y), make_float2(wB.z, wB.w) };
                #pragma unroll
                for (int r = 0; r < 8; r++) {
                    float av = (&ar[r].x)[kk];
                    float2 pa = make_float2(av, av);
                    #pragma unroll
                    for (int c = 0; c < 4; c++) acc[r][c] = ffma2(pa, wv[c], acc[r][c]);
                }
            }
        }
        __syncthreads();
        buf ^= 1;
    }

    // ---- epilogue ----
    float4 b0 = *reinterpret_cast<const float4*>(bias + c0);
    float4 b1 = *reinterpret_cast<const float4*>(bias + c0 + 4);
    float bv[8] = {b0.x, b0.y, b0.z, b0.w, b1.x, b1.y, b1.z, b1.w};

    if (mode == 0) {
        #pragma unroll
        for (int i = 0; i < 8; i++) {
            int gr = r0 + ry + i;
            if (gr < Nn) {
                float cv = cnt[gr];
                float rc = 1.0f / fmaxf(cv, 1.0f);
                float v[8];
                #pragma unroll
                for (int c = 0; c < 4; c++) {
                    v[2*c]   = (acc[i][c].x + cv * bv[2*c])   * rc;
                    v[2*c+1] = (acc[i][c].y + cv * bv[2*c+1]) * rc;
                }
                *reinterpret_cast<float4*>(out + gr*Hh + c0)     = make_float4(v[0],v[1],v[2],v[3]);
                *reinterpret_cast<float4*>(out + gr*Hh + c0 + 4) = make_float4(v[4],v[5],v[6],v[7]);
            }
        }
    } else if (mode == 1) {
        float cs[8], cq[8];
        #pragma unroll
        for (int j = 0; j < 8; j++) { cs[j] = 0.f; cq[j] = 0.f; }
        #pragma unroll
        for (int i = 0; i < 8; i++) {
            int gr = r0 + ry + i;
            if (gr < Nn) {
                float v[8];
                #pragma unroll
                for (int c = 0; c < 4; c++) {
                    v[2*c]   = acc[i][c].x + bv[2*c];
                    v[2*c+1] = acc[i][c].y + bv[2*c+1];
                }
                *reinterpret_cast<float4*>(out + gr*Hh + c0)     = make_float4(v[0],v[1],v[2],v[3]);
                *reinterpret_cast<float4*>(out + gr*Hh + c0 + 4) = make_float4(v[4],v[5],v[6],v[7]);
                #pragma unroll
                for (int j = 0; j < 8; j++) { cs[j] += v[j]; cq[j] += v[j]*v[j]; }
            }
        }
        float (*red)[Hh] = reinterpret_cast<float(*)[Hh]>(sm);
        #pragma unroll
        for (int j = 0; j < 8; j++) red[ty][c0 + j] = cs[j];
        __syncthreads();
        if (t < Hh) {
            float s = 0.f;
            #pragma unroll
            for (int y = 0; y < 16; y++) s += red[y][t];
            atomicAdd(bnsum + t, s);
        }
        __syncthreads();
        #pragma unroll
        for (int j = 0; j < 8; j++) red[ty][c0 + j] = cq[j];
        __syncthreads();
        if (t < Hh) {
            float s = 0.f;
            #pragma unroll
            for (int y = 0; y < 16; y++) s += red[y][t];
            atomicAdd(bnsq + t, s);
        }
    } else {
        #pragma unroll
        for (int i = 0; i < 8; i++) {
            int gr = r0 + ry + i;
            if (gr < Nn) {
                float v[8];
                #pragma unroll
                for (int c = 0; c < 4; c++) {
                    v[2*c]   = fmaxf(acc[i][c].x + bv[2*c],   0.f);
                    v[2*c+1] = fmaxf(acc[i][c].y + bv[2*c+1], 0.f);
                }
                *reinterpret_cast<float4*>(out + gr*Hh + c0)     = make_float4(v[0],v[1],v[2],v[3]);
                *reinterpret_cast<float4*>(out + gr*Hh + c0 + 4) = make_float4(v[4],v[5],v[6],v[7]);
            }
        }
    }
}

// ---------------- BN finalize ----------------
__global__ void bn_finalize(const float* __restrict__ g, const float* __restrict__ be) {
    int c = threadIdx.x;
    float m = g_bn[c] * (1.0f / (float)Nn);
    float q = g_bn[128 + c] * (1.0f / (float)Nn);
    float v = fmaxf(q - m*m, 0.f);
    float inv = rsqrtf(v + EPSf);
    float sc = g[c] * inv;
    g_bn[256 + c] = sc;
    g_bn[384 + c] = be[c] - m * sc;
    g_bn[c] = 0.f;
    g_bn[128 + c] = 0.f;
}

// ---------------- h = relu(scale*z + shift) ----------------
__global__ void bn_apply(const float* __restrict__ z, float* __restrict__ h) {
    int i4 = blockIdx.x * blockDim.x + threadIdx.x;
    if (i4 >= Nn * 32) return;
    int c4 = i4 & 31;
    float4 zz = reinterpret_cast<const float4*>(z)[i4];
    float4 sc = reinterpret_cast<const float4*>(g_bn + 256)[c4];
    float4 sh = reinterpret_cast<const float4*>(g_bn + 384)[c4];
    float4 v;
    v.x = fmaxf(sc.x*zz.x + sh.x, 0.f);
    v.y = fmaxf(sc.y*zz.y + sh.y, 0.f);
    v.z = fmaxf(sc.z*zz.z + sh.z, 0.f);
    v.w = fmaxf(sc.w*zz.w + sh.w, 0.f);
    reinterpret_cast<float4*>(h)[i4] = v;
}

// ---------------- head ----------------
__global__ void final_out(const float* __restrict__ z, const float* __restrict__ wout,
                          const float* __restrict__ bout, float* __restrict__ out) {
    int w = blockIdx.x * 8 + (threadIdx.x >> 5);
    if (w >= Nn) return;
    int lane = threadIdx.x & 31;
    float s = 0.f;
    #pragma unroll
    for (int j = 0; j < 4; j++) {
        int c = lane + 32*j;
        float v = fmaxf(g_bn[256 + c] * z[w*Hh + c] + g_bn[384 + c], 0.f);
        s += v * wout[c];
    }
    #pragma unroll
    for (int o = 16; o > 0; o >>= 1) s += __shfl_xor_sync(0xffffffffu, s, o);
    if (lane == 0) out[w] = s + bout[0];
}

// ---------------- launch ----------------
extern "C" void kernel_launch(void* const* d_in, const int* in_sizes, int n_in,
                              void* d_out, int out_size) {
    const float* x      = (const float*)d_in[0];
    const int*   ei     = (const int*)  d_in[1];
    const float* ea     = (const float*)d_in[2];
    const float* w_int  = (const float*)d_in[3];
    const float* b_int  = (const float*)d_in[4];
    const float* w_pre  = (const float*)d_in[5];
    const float* b_pre  = (const float*)d_in[6];
    const float* gpre   = (const float*)d_in[7];
    const float* bepre  = (const float*)d_in[8];
    const float* c1w    = (const float*)d_in[9];
    const float* c1b    = (const float*)d_in[10];
    const float* c2w    = (const float*)d_in[11];
    const float* c2b    = (const float*)d_in[12];
    const float* w_post = (const float*)d_in[13];
    const float* b_post = (const float*)d_in[14];
    const float* gpost  = (const float*)d_in[15];
    const float* bepost = (const float*)d_in[16];
    const float* w_out  = (const float*)d_in[17];
    const float* b_out  = (const float*)d_in[18];
    float* out = (float*)d_out;

    float *B0, *B1, *B2, *B3, *BX, *cnt, *bn;
    cudaGetSymbolAddress((void**)&B0,  g_B0);
    cudaGetSymbolAddress((void**)&B1,  g_B1);
    cudaGetSymbolAddress((void**)&B2,  g_B2);
    cudaGetSymbolAddress((void**)&B3,  g_B3);
    cudaGetSymbolAddress((void**)&BX,  g_BX);
    cudaGetSymbolAddress((void**)&cnt, g_cnt);
    cudaGetSymbolAddress((void**)&bn,  g_bn);

    cudaFuncSetAttribute(gemm2, cudaFuncAttributeMaxDynamicSharedMemorySize, 65536);
    const int SMB = 65536;

    const int EB = (Ee + 255) / 256;
    const int GB = (Nn + 127) / 128;
    const int WB = (Nn + 7) / 8;
    const int NB = (Nn + 255) / 256;

    // CSR build
    zero_init<<<NB, 256>>>();
    hist<<<EB, 256>>>(ei);
    scan1<<<NPART, 1024>>>();
    scan2<<<1, 128>>>();
    scan3_dis<<<NB, 256>>>();
    fill_csr<<<EB, 256>>>(ei);

    // interaction gather + GEMM -> B1
    gather_interact<<<WB, 256>>>(x, ea);
    gemm2<<<GB, 256, SMB>>>(B0, w_int, 128, BX, w_int + 128*128, 16,
                            nullptr, nullptr, 0, b_int, 0, cnt,
                            B1, nullptr, nullptr);
    // pre
    gemm2<<<GB, 256, SMB>>>(B1, w_pre, 128, nullptr, nullptr, 0,
                            nullptr, nullptr, 0, b_pre, 1, nullptr,
                            B2, bn, bn + 128);
    bn_finalize<<<1, 128>>>(gpre, bepre);
    bn_apply<<<(Nn*32 + 255)/256, 256>>>(B2, B1);   // B1 = h

    // cheb1
    gather_lhat<<<WB, 256>>>(B1, B0, nullptr, 1.0f);   // T1
    gather_lhat<<<WB, 256>>>(B0, B3, B1, 2.0f);        // T2 = 2*lhat(T1) - h
    gemm2<<<GB, 256, SMB>>>(B1, c1w, 128, B0, c1w + 16384, 128,
                            B3, c1w + 32768, 128, c1b, 2, nullptr,
                            B2, nullptr, nullptr);     // B2 = h2

    // cheb2
    gather_lhat<<<WB, 256>>>(B2, B0, nullptr, 1.0f);
    gather_lhat<<<WB, 256>>>(B0, B3, B2, 2.0f);
    gemm2<<<GB, 256, SMB>>>(B2, c2w, 128, B0, c2w + 16384, 128,
                            B3, c2w + 32768, 128, c2b, 2, nullptr,
                            B1, nullptr, nullptr);     // B1 = h3

    // post + head
    gemm2<<<GB, 256, SMB>>>(B1, w_post, 128, nullptr, nullptr, 0,
                            nullptr, nullptr, 0, b_post, 1, nullptr,
                            B2, bn, bn + 128);
    bn_finalize<<<1, 128>>>(gpost, bepost);
    final_out<<<WB, 256>>>(B2, w_out, b_out, out);
}